// round 6
// baseline (speedup 1.0000x reference)
#include <cuda_runtime.h>

// LSTMModel: B=1024, T=256, I=5, H=64, L=3, O=1, fp32.
// R5: lstm_rec k-split -> 512-thread CTAs (thread = (gate col, k-half)),
// 32 weight regs/thread, partial-gate smem buffers summed in epilogue.
// 2 CTAs/SM => 32 warps/SM, halved per-warp dependency chains.
// Balanced 304-CTA grid (112x4 + 192x3 rows). Templated mode.

#define B_SZ 1024
#define T_SZ 256
#define I_SZ 5
#define H_SZ 64
#define G_SZ 256   // 4*H
#define N4   112           // CTAs carrying 4 rows; rest carry 3
#define GRID_REC 304       // 112*4 + 192*3 = 1024

typedef unsigned long long u64;

__device__ float g_xg[(size_t)B_SZ * T_SZ * G_SZ];  // gate preactivations (layers 1,2)
__device__ float g_h [(size_t)B_SZ * T_SZ * H_SZ];  // layer outputs / h_last
__device__ float g_wT[H_SZ * G_SZ];                 // transposed w_ih (layers 1/2)

__device__ __forceinline__ u64 ffma2(u64 a, u64 b, u64 c) {
    u64 d;
    asm("fma.rn.f32x2 %0, %1, %2, %3;" : "=l"(d) : "l"(a), "l"(b), "l"(c));
    return d;
}
__device__ __forceinline__ u64 pack2(float lo, float hi) {
    u64 d;
    asm("mov.b64 %0, {%1, %2};" : "=l"(d) : "f"(lo), "f"(hi));
    return d;
}
__device__ __forceinline__ float sum2(u64 v) {
    float lo, hi;
    asm("mov.b64 {%0, %1}, %2;" : "=f"(lo), "=f"(hi) : "l"(v));
    return lo + hi;
}

__device__ __forceinline__ float sigf(float x) {
    return __fdividef(1.0f, 1.0f + __expf(-x));
}
__device__ __forceinline__ float tanh_fast(float x) {
    float ax = fabsf(x);
    float e  = __expf(-2.0f * ax);
    float r  = __fdividef(1.0f - e, 1.0f + e);
    return copysignf(r, x);
}

// ---------------------------------------------------------------------------
// Transpose w_ih [256,64] -> g_wT [64,256].
// ---------------------------------------------------------------------------
__global__ __launch_bounds__(256) void transpose_w(const float* __restrict__ w)
{
    int idx = blockIdx.x * 256 + threadIdx.x;
    int g = idx >> 6, k = idx & 63;
    g_wT[k * G_SZ + g] = w[idx];
}

// ---------------------------------------------------------------------------
// Layers 1/2 input projection: [262144,64] @ [64,256] + bias -> g_xg.
// (unchanged from R4: dup-pair input tile, single sync, 2 CTAs/SM)
// ---------------------------------------------------------------------------
#define XG_W_PITCH 260
#define XG_SMEM_BYTES (64 * 64 * 8 + 64 * XG_W_PITCH * 4)

__global__ __launch_bounds__(256, 2) void xg_gemm64(
    const float* __restrict__ b_ih, const float* __restrict__ b_hh)
{
    extern __shared__ __align__(16) unsigned char smraw[];
    u64   (*a2_s)[64]        = (u64(*)[64])smraw;
    float (*w_s)[XG_W_PITCH] = (float(*)[XG_W_PITCH])(smraw + 64 * 64 * 8);

    const int t    = threadIdx.x;
    const int row0 = blockIdx.x * 64;
    const int tcol = t & 31, trow = t >> 5;
    const int g0   = tcol * 8;

#pragma unroll
    for (int u = 0; u < 4; u++) {
        int v = u * 256 + t;
        int r = v >> 4, kq = v & 15;
        float4 d = *(const float4*)&g_h[(size_t)(row0 + r) * H_SZ + kq * 4];
        ulonglong2 e0, e1;
        e0.x = pack2(d.x, d.x); e0.y = pack2(d.y, d.y);
        e1.x = pack2(d.z, d.z); e1.y = pack2(d.w, d.w);
        *(ulonglong2*)&a2_s[r][kq * 4]     = e0;
        *(ulonglong2*)&a2_s[r][kq * 4 + 2] = e1;
    }
#pragma unroll
    for (int u = 0; u < 16; u++) {
        int v = u * 256 + t;
        int k = v >> 6, gq = v & 63;
        float4 d = *(const float4*)&g_wT[k * G_SZ + gq * 4];
        *(float4*)&w_s[k][gq * 4] = d;
    }

    u64 acc2[8][4];
#pragma unroll
    for (int jp = 0; jp < 4; jp++) {
        float blo = b_ih[g0 + 2 * jp]     + b_hh[g0 + 2 * jp];
        float bhi = b_ih[g0 + 2 * jp + 1] + b_hh[g0 + 2 * jp + 1];
        u64 bp = pack2(blo, bhi);
#pragma unroll
        for (int ii = 0; ii < 8; ii++) acc2[ii][jp] = bp;
    }

    __syncthreads();

#pragma unroll 4
    for (int k = 0; k < 64; k++) {
        u64 adup[8];
#pragma unroll
        for (int ii = 0; ii < 8; ii++)
            adup[ii] = a2_s[trow * 8 + ii][k];
        ulonglong2 bv0 = *(const ulonglong2*)&w_s[k][g0];
        ulonglong2 bv1 = *(const ulonglong2*)&w_s[k][g0 + 4];
        u64 bp[4] = {bv0.x, bv0.y, bv1.x, bv1.y};
#pragma unroll
        for (int ii = 0; ii < 8; ii++)
#pragma unroll
            for (int jp = 0; jp < 4; jp++)
                acc2[ii][jp] = ffma2(adup[ii], bp[jp], acc2[ii][jp]);
    }

#pragma unroll
    for (int ii = 0; ii < 8; ii++) {
        size_t base = (size_t)(row0 + trow * 8 + ii) * G_SZ + g0;
        ulonglong2 o0, o1;
        o0.x = acc2[ii][0]; o0.y = acc2[ii][1];
        o1.x = acc2[ii][2]; o1.y = acc2[ii][3];
        *(ulonglong2*)&g_xg[base]     = o0;
        *(ulonglong2*)&g_xg[base + 4] = o1;
    }
}

// ---------------------------------------------------------------------------
// Recurrent scan, one layer. 304 CTAs x 512 threads, 2 CTAs/SM.
// Thread t = (col = t&255, s = t>>8): computes the k-half [32s,32s+32) of
// gate column `col` for up to 4 rows; w_hh half-row register-resident (32
// regs as 16 f32x2 pairs); h broadcast from smem. Partial sums land in
// gates_p[s]; epilogue threads (t<256) add halves and run one cell each.
// MODE 0: layer 0, xg fused (K=5), write full h seq.
// MODE 1: read g_xg, write full h seq.  MODE 2: read g_xg, write last only.
// ---------------------------------------------------------------------------
template<int MODE>
__global__ __launch_bounds__(512, 2) void lstm_rec(
    const float* __restrict__ w_hh,
    const float* __restrict__ x,      // MODE 0 only
    const float* __restrict__ w_ih,   // MODE 0 only [256,5]
    const float* __restrict__ b_ih,   // MODE 0 only
    const float* __restrict__ b_hh)   // MODE 0 only
{
    __shared__ __align__(16) float h_s[4][H_SZ];        // 1 KB
    __shared__ float gates_p[2][4][G_SZ];               // 8 KB
    __shared__ float xs[2][4][8];                       // MODE-0 x staging
    const int t    = threadIdx.x;
    const int col  = t & 255;            // gate column
    const int s    = t >> 8;             // k-half
    const int bid  = blockIdx.x;
    const bool r4  = (bid < N4);
    const int b0   = r4 ? bid * 4 : N4 * 4 + (bid - N4) * 3;
    const int rows = r4 ? 4 : 3;

    // register-resident weight pairs: w_hh[col][32s .. 32s+32)
    u64 w2[16];
    {
        const ulonglong2* wv = (const ulonglong2*)(w_hh + col * H_SZ + s * 32);
#pragma unroll
        for (int q = 0; q < 8; q++) {
            ulonglong2 v = wv[q];
            w2[2 * q]     = v.x;
            w2[2 * q + 1] = v.y;
        }
    }

    // MODE-0: input weights + bias + step-0 x staging (khalf 0 only)
    float wx[MODE == 0 ? I_SZ : 1];
    float bias = 0.0f;
    if (MODE == 0 && s == 0) {
#pragma unroll
        for (int k = 0; k < I_SZ; k++) wx[k] = w_ih[col * I_SZ + k];
        bias = b_ih[col] + b_hh[col];
        if (t < 4 * I_SZ) {
            int r = t / I_SZ, k = t % I_SZ;
            if (r < rows)
                xs[0][r][k] = x[((size_t)(b0 + r) * T_SZ) * I_SZ + k];
        }
    }

    if (t < 256) ((float*)h_s)[t] = 0.0f;

    const int re = t >> 6, je = t & 63;            // epilogue cell (t<256)
    const bool cell = (t < rows * 64);
    float c = 0.0f;

    // MODE 1/2: khalf-0 prefetches xg for step 0 (coalesced)
    float xn[4];
    if (MODE != 0 && s == 0) {
#pragma unroll
        for (int r = 0; r < 3; r++)
            xn[r] = g_xg[((size_t)(b0 + r) * T_SZ) * G_SZ + col];
        if (r4) xn[3] = g_xg[((size_t)(b0 + 3) * T_SZ) * G_SZ + col];
    }

    __syncthreads();

    for (int step = 0; step < T_SZ; step++) {
        u64 acc2[4];
        if (MODE == 0) {
            const int cur = step & 1;
            float a0 = 0.f, a1 = 0.f, a2v = 0.f, a3 = 0.f;
            if (s == 0) {
                a0 = bias; a1 = bias; a2v = bias; a3 = bias;
#pragma unroll
                for (int k = 0; k < I_SZ; k++) {
                    a0  = fmaf(xs[cur][0][k], wx[k], a0);
                    a1  = fmaf(xs[cur][1][k], wx[k], a1);
                    a2v = fmaf(xs[cur][2][k], wx[k], a2v);
                    a3  = fmaf(xs[cur][3][k], wx[k], a3);
                }
                if (step + 1 < T_SZ && t < 4 * I_SZ) {
                    int r = t / I_SZ, k = t % I_SZ;
                    if (r < rows)
                        xs[cur ^ 1][r][k] =
                            x[((size_t)(b0 + r) * T_SZ + step + 1) * I_SZ + k];
                }
            }
            acc2[0] = pack2(a0, 0.0f);  acc2[1] = pack2(a1, 0.0f);
            acc2[2] = pack2(a2v, 0.0f); acc2[3] = pack2(a3, 0.0f);
        } else {
            if (s == 0) {
#pragma unroll
                for (int r = 0; r < 4; r++) acc2[r] = pack2(xn[r], 0.0f);
                if (step + 1 < T_SZ) {
#pragma unroll
                    for (int r = 0; r < 3; r++)
                        xn[r] = g_xg[((size_t)(b0 + r) * T_SZ + step + 1) * G_SZ + col];
                    if (r4)
                        xn[3] = g_xg[((size_t)(b0 + 3) * T_SZ + step + 1) * G_SZ + col];
                }
            } else {
#pragma unroll
                for (int r = 0; r < 4; r++) acc2[r] = pack2(0.0f, 0.0f);
            }
        }

        // half-GEMM: gates_p[s][r][col] = sum_{k in half s} h[r][k]*w[col][k]
        const ulonglong2* h2 = (const ulonglong2*)&h_s[0][s * 32];
#pragma unroll
        for (int q = 0; q < 8; q++) {
            const u64 wa = w2[2 * q], wb = w2[2 * q + 1];
            ulonglong2 p0 = h2[0 * 16 + q];
            acc2[0] = ffma2(p0.x, wa, acc2[0]);
            acc2[0] = ffma2(p0.y, wb, acc2[0]);
            ulonglong2 p1 = h2[1 * 16 + q];
            acc2[1] = ffma2(p1.x, wa, acc2[1]);
            acc2[1] = ffma2(p1.y, wb, acc2[1]);
            ulonglong2 p2 = h2[2 * 16 + q];
            acc2[2] = ffma2(p2.x, wa, acc2[2]);
            acc2[2] = ffma2(p2.y, wb, acc2[2]);
        }
        if (r4) {
#pragma unroll
            for (int q = 0; q < 8; q++) {
                ulonglong2 p3 = h2[3 * 16 + q];
                acc2[3] = ffma2(p3.x, w2[2 * q],     acc2[3]);
                acc2[3] = ffma2(p3.y, w2[2 * q + 1], acc2[3]);
            }
        }
        gates_p[s][0][col] = sum2(acc2[0]);
        gates_p[s][1][col] = sum2(acc2[1]);
        gates_p[s][2][col] = sum2(acc2[2]);
        if (r4) gates_p[s][3][col] = sum2(acc2[3]);
        __syncthreads();

        // elementwise LSTM cell: one cell per thread (first 8 warps)
        if (cell) {
            float gi = gates_p[0][re][je]       + gates_p[1][re][je];
            float gf = gates_p[0][re][64 + je]  + gates_p[1][re][64 + je];
            float gg = gates_p[0][re][128 + je] + gates_p[1][re][128 + je];
            float go = gates_p[0][re][192 + je] + gates_p[1][re][192 + je];
            float iv = sigf(gi);
            float fv = sigf(gf);
            float gv = tanh_fast(gg);
            float ov = sigf(go);
            c = fmaf(fv, c, iv * gv);
            float hv = ov * tanh_fast(c);
            h_s[re][je] = hv;
            if (MODE != 2)
                g_h[((size_t)(b0 + re) * T_SZ + step) * H_SZ + je] = hv;
            else if (step == T_SZ - 1)
                g_h[(size_t)(b0 + re) * H_SZ + je] = hv;
        }
        __syncthreads();
    }
}

// ---------------------------------------------------------------------------
// Final FC: out[b] = h_last[b,:] . w_fc + b_fc   (O=1)
// ---------------------------------------------------------------------------
__global__ __launch_bounds__(256) void fc_kernel(const float* __restrict__ wfc,
                                                 const float* __restrict__ bfc,
                                                 float* __restrict__ out)
{
    int b = blockIdx.x * 256 + threadIdx.x;
    float acc = bfc[0];
#pragma unroll
    for (int q = 0; q < 16; q++) {
        float4 hv = *(const float4*)&g_h[b * H_SZ + q * 4];
        float4 wv = *(const float4*)&wfc[q * 4];
        acc = fmaf(hv.x, wv.x, acc);
        acc = fmaf(hv.y, wv.y, acc);
        acc = fmaf(hv.z, wv.z, acc);
        acc = fmaf(hv.w, wv.w, acc);
    }
    out[b] = acc;
}

// ---------------------------------------------------------------------------
extern "C" void kernel_launch(void* const* d_in, const int* in_sizes, int n_in,
                              void* d_out, int out_size)
{
    (void)in_sizes; (void)n_in; (void)out_size;
    const float* x     = (const float*)d_in[0];
    const float* w_ih0 = (const float*)d_in[1];
    const float* w_hh0 = (const float*)d_in[2];
    const float* b_ih0 = (const float*)d_in[3];
    const float* b_hh0 = (const float*)d_in[4];
    const float* w_ih1 = (const float*)d_in[5];
    const float* w_hh1 = (const float*)d_in[6];
    const float* b_ih1 = (const float*)d_in[7];
    const float* b_hh1 = (const float*)d_in[8];
    const float* w_ih2 = (const float*)d_in[9];
    const float* w_hh2 = (const float*)d_in[10];
    const float* b_ih2 = (const float*)d_in[11];
    const float* b_hh2 = (const float*)d_in[12];
    const float* w_fc  = (const float*)d_in[13];
    const float* b_fc  = (const float*)d_in[14];
    float* out = (float*)d_out;

    const int NROWS = B_SZ * T_SZ;  // 262144

    cudaFuncSetAttribute(xg_gemm64, cudaFuncAttributeMaxDynamicSharedMemorySize,
                         XG_SMEM_BYTES);

    // layer 0 (xg fused into rec)
    lstm_rec<0><<<GRID_REC, 512>>>(w_hh0, x, w_ih0, b_ih0, b_hh0);

    // layer 1
    transpose_w<<<64, 256>>>(w_ih1);
    xg_gemm64<<<NROWS / 64, 256, XG_SMEM_BYTES>>>(b_ih1, b_hh1);
    lstm_rec<1><<<GRID_REC, 512>>>(w_hh1, nullptr, nullptr, nullptr, nullptr);

    // layer 2 (only last timestep's h needed downstream)
    transpose_w<<<64, 256>>>(w_ih2);
    xg_gemm64<<<NROWS / 64, 256, XG_SMEM_BYTES>>>(b_ih2, b_hh2);
    lstm_rec<2><<<GRID_REC, 512>>>(w_hh2, nullptr, nullptr, nullptr, nullptr);

    // final projection
    fc_kernel<<<B_SZ / 256, 256>>>(w_fc, b_fc, out);
}

// round 7
// speedup vs baseline: 1.1816x; 1.1816x over previous
#include <cuda_runtime.h>

// LSTMModel: B=1024, T=256, I=5, H=64, L=3, O=1, fp32.
// R6: lstm_rec software-pipelined across row groups G0={0,1}, G1={2,3}:
//   phase A(t): GEMM G1(t)   + epilogue G0(t)
//   phase B(t): GEMM G0(t+1) + epilogue G1(t)
// Every phase mixes FFMA2 GEMM with MUFU epilogue -> latency overlap,
// still 2 barriers/step. Balanced 304-CTA grid (112x4 + 192x3 rows),
// 2 CTAs/SM. xg_gemm64 / transpose / fc unchanged from R4.

#define B_SZ 1024
#define T_SZ 256
#define I_SZ 5
#define H_SZ 64
#define G_SZ 256   // 4*H
#define N4   112           // CTAs carrying 4 rows; rest carry 3
#define GRID_REC 304       // 112*4 + 192*3 = 1024

typedef unsigned long long u64;

__device__ float g_xg[(size_t)B_SZ * T_SZ * G_SZ];  // gate preactivations (layers 1,2)
__device__ float g_h [(size_t)B_SZ * T_SZ * H_SZ];  // layer outputs / h_last
__device__ float g_wT[H_SZ * G_SZ];                 // transposed w_ih (layers 1/2)

__device__ __forceinline__ u64 ffma2(u64 a, u64 b, u64 c) {
    u64 d;
    asm("fma.rn.f32x2 %0, %1, %2, %3;" : "=l"(d) : "l"(a), "l"(b), "l"(c));
    return d;
}
__device__ __forceinline__ u64 pack2(float lo, float hi) {
    u64 d;
    asm("mov.b64 %0, {%1, %2};" : "=l"(d) : "f"(lo), "f"(hi));
    return d;
}
__device__ __forceinline__ float sum2(u64 v) {
    float lo, hi;
    asm("mov.b64 {%0, %1}, %2;" : "=f"(lo), "=f"(hi) : "l"(v));
    return lo + hi;
}

__device__ __forceinline__ float sigf(float x) {
    return __fdividef(1.0f, 1.0f + __expf(-x));
}
__device__ __forceinline__ float tanh_fast(float x) {
    float ax = fabsf(x);
    float e  = __expf(-2.0f * ax);
    float r  = __fdividef(1.0f - e, 1.0f + e);
    return copysignf(r, x);
}

// ---------------------------------------------------------------------------
// Transpose w_ih [256,64] -> g_wT [64,256].
// ---------------------------------------------------------------------------
__global__ __launch_bounds__(256) void transpose_w(const float* __restrict__ w)
{
    int idx = blockIdx.x * 256 + threadIdx.x;
    int g = idx >> 6, k = idx & 63;
    g_wT[k * G_SZ + g] = w[idx];
}

// ---------------------------------------------------------------------------
// Layers 1/2 input projection (unchanged from R4).
// ---------------------------------------------------------------------------
#define XG_W_PITCH 260
#define XG_SMEM_BYTES (64 * 64 * 8 + 64 * XG_W_PITCH * 4)

__global__ __launch_bounds__(256, 2) void xg_gemm64(
    const float* __restrict__ b_ih, const float* __restrict__ b_hh)
{
    extern __shared__ __align__(16) unsigned char smraw[];
    u64   (*a2_s)[64]        = (u64(*)[64])smraw;
    float (*w_s)[XG_W_PITCH] = (float(*)[XG_W_PITCH])(smraw + 64 * 64 * 8);

    const int t    = threadIdx.x;
    const int row0 = blockIdx.x * 64;
    const int tcol = t & 31, trow = t >> 5;
    const int g0   = tcol * 8;

#pragma unroll
    for (int u = 0; u < 4; u++) {
        int v = u * 256 + t;
        int r = v >> 4, kq = v & 15;
        float4 d = *(const float4*)&g_h[(size_t)(row0 + r) * H_SZ + kq * 4];
        ulonglong2 e0, e1;
        e0.x = pack2(d.x, d.x); e0.y = pack2(d.y, d.y);
        e1.x = pack2(d.z, d.z); e1.y = pack2(d.w, d.w);
        *(ulonglong2*)&a2_s[r][kq * 4]     = e0;
        *(ulonglong2*)&a2_s[r][kq * 4 + 2] = e1;
    }
#pragma unroll
    for (int u = 0; u < 16; u++) {
        int v = u * 256 + t;
        int k = v >> 6, gq = v & 63;
        float4 d = *(const float4*)&g_wT[k * G_SZ + gq * 4];
        *(float4*)&w_s[k][gq * 4] = d;
    }

    u64 acc2[8][4];
#pragma unroll
    for (int jp = 0; jp < 4; jp++) {
        float blo = b_ih[g0 + 2 * jp]     + b_hh[g0 + 2 * jp];
        float bhi = b_ih[g0 + 2 * jp + 1] + b_hh[g0 + 2 * jp + 1];
        u64 bp = pack2(blo, bhi);
#pragma unroll
        for (int ii = 0; ii < 8; ii++) acc2[ii][jp] = bp;
    }

    __syncthreads();

#pragma unroll 4
    for (int k = 0; k < 64; k++) {
        u64 adup[8];
#pragma unroll
        for (int ii = 0; ii < 8; ii++)
            adup[ii] = a2_s[trow * 8 + ii][k];
        ulonglong2 bv0 = *(const ulonglong2*)&w_s[k][g0];
        ulonglong2 bv1 = *(const ulonglong2*)&w_s[k][g0 + 4];
        u64 bp[4] = {bv0.x, bv0.y, bv1.x, bv1.y};
#pragma unroll
        for (int ii = 0; ii < 8; ii++)
#pragma unroll
            for (int jp = 0; jp < 4; jp++)
                acc2[ii][jp] = ffma2(adup[ii], bp[jp], acc2[ii][jp]);
    }

#pragma unroll
    for (int ii = 0; ii < 8; ii++) {
        size_t base = (size_t)(row0 + trow * 8 + ii) * G_SZ + g0;
        ulonglong2 o0, o1;
        o0.x = acc2[ii][0]; o0.y = acc2[ii][1];
        o1.x = acc2[ii][2]; o1.y = acc2[ii][3];
        *(ulonglong2*)&g_xg[base]     = o0;
        *(ulonglong2*)&g_xg[base + 4] = o1;
    }
}

// ---------------------------------------------------------------------------
// LSTM cell epilogue for one (row re, hidden je) given its gate row.
// ---------------------------------------------------------------------------
__device__ __forceinline__ float cell_update(const float* grow, int je, float& c)
{
    float iv = sigf(grow[je]);
    float fv = sigf(grow[64 + je]);
    float gv = tanh_fast(grow[128 + je]);
    float ov = sigf(grow[192 + je]);
    c = fmaf(fv, c, iv * gv);
    return ov * tanh_fast(c);
}

// ---------------------------------------------------------------------------
// Recurrent scan, one layer. 304 CTAs x 256 threads, 2 CTAs/SM.
// Thread t = gate column; w_hh row t register-resident (32 f32x2 pairs).
// Row groups G0={0,1}, G1={2,(3)}. Per step:
//   phase A(t): GEMM G1(t) [h_s rows 2,3] + epilogue G0(t) [gates_s rows 0,1]
//   phase B(t): GEMM G0(t+1) [h_s rows 0,1] + epilogue G1(t) [gates_s rows 2,3]
// MODE 0: layer 0, xg fused (K=5, x staged in double-buffered smem).
// MODE 1: read g_xg, write full h seq.  MODE 2: read g_xg, write last only.
// ---------------------------------------------------------------------------
template<int MODE>
__global__ __launch_bounds__(256, 2) void lstm_rec(
    const float* __restrict__ w_hh,
    const float* __restrict__ x,      // MODE 0 only
    const float* __restrict__ w_ih,   // MODE 0 only [256,5]
    const float* __restrict__ b_ih,   // MODE 0 only
    const float* __restrict__ b_hh)   // MODE 0 only
{
    __shared__ __align__(16) float h_s[4][H_SZ];     // 1 KB
    __shared__ float gates_s[4][G_SZ];               // 4 KB
    __shared__ float xs[2][4][8];                    // MODE-0 x staging
    const int t    = threadIdx.x;                    // gate column
    const int bid  = blockIdx.x;
    const bool r4  = (bid < N4);
    const int b0   = r4 ? bid * 4 : N4 * 4 + (bid - N4) * 3;
    const int rows = r4 ? 4 : 3;

    // register-resident recurrent weight pairs (w_hh row t)
    u64 w2[32];
    {
        const ulonglong2* wv = (const ulonglong2*)(w_hh + t * H_SZ);
#pragma unroll
        for (int q = 0; q < 16; q++) {
            ulonglong2 v = wv[q];
            w2[2 * q]     = v.x;
            w2[2 * q + 1] = v.y;
        }
    }

    // MODE-0: input weights + bias + step-0 x staging
    float wx[MODE == 0 ? I_SZ : 1];
    float bias = 0.0f;
    if (MODE == 0) {
#pragma unroll
        for (int k = 0; k < I_SZ; k++) wx[k] = w_ih[t * I_SZ + k];
        bias = b_ih[t] + b_hh[t];
        if (t < 4 * I_SZ) {
            int r = t / I_SZ, k = t % I_SZ;
            if (r < rows)
                xs[0][r][k] = x[((size_t)(b0 + r) * T_SZ) * I_SZ + k];
        }
    }

    ((float*)h_s)[t] = 0.0f;   // 256 floats exactly

    const int re = t >> 6, je = t & 63;     // epilogue cell
    const bool cellG0 = (re < 2);
    const bool cellG1 = (re >= 2) && (re < rows);
    float c = 0.0f;

    // xg prefetch regs (MODE 1/2): xnA = G1 rows step t, xnB = G0 rows step t+1
    float xnA[2] = {0.f, 0.f}, xnB[2] = {0.f, 0.f};
    float xnP0 = 0.f, xnP1 = 0.f;   // prologue: G0 rows step 0
    if (MODE != 0) {
        xnP0   = g_xg[((size_t)(b0 + 0) * T_SZ) * G_SZ + t];
        xnP1   = g_xg[((size_t)(b0 + 1) * T_SZ) * G_SZ + t];
        xnA[0] = g_xg[((size_t)(b0 + 2) * T_SZ) * G_SZ + t];
        if (r4) xnA[1] = g_xg[((size_t)(b0 + 3) * T_SZ) * G_SZ + t];
        xnB[0] = g_xg[((size_t)(b0 + 0) * T_SZ + 1) * G_SZ + t];
        xnB[1] = g_xg[((size_t)(b0 + 1) * T_SZ + 1) * G_SZ + t];
    }

    __syncthreads();

    // prologue: gates G0(0) = xg only (h == 0)
    if (MODE == 0) {
        float a0 = bias, a1 = bias;
#pragma unroll
        for (int k = 0; k < I_SZ; k++) {
            a0 = fmaf(xs[0][0][k], wx[k], a0);
            a1 = fmaf(xs[0][1][k], wx[k], a1);
        }
        gates_s[0][t] = a0;
        gates_s[1][t] = a1;
    } else {
        gates_s[0][t] = xnP0;
        gates_s[1][t] = xnP1;
    }
    __syncthreads();

    for (int step = 0; step < T_SZ; step++) {
        // ---------------- phase A: GEMM G1(step) + epilogue G0(step) --------
        {
            u64 a0, a1;
            if (MODE == 0) {
                const int cur = step & 1;
                float s0 = bias, s1 = bias;
#pragma unroll
                for (int k = 0; k < I_SZ; k++) {
                    s0 = fmaf(xs[cur][2][k], wx[k], s0);
                    s1 = fmaf(xs[cur][3][k], wx[k], s1);
                }
                a0 = pack2(s0, 0.0f);
                a1 = pack2(s1, 0.0f);
                // stage x(step+1) for both groups into the other buffer
                if (step + 1 < T_SZ && t < 4 * I_SZ) {
                    int r = t / I_SZ, k = t % I_SZ;
                    if (r < rows)
                        xs[cur ^ 1][r][k] =
                            x[((size_t)(b0 + r) * T_SZ + step + 1) * I_SZ + k];
                }
            } else {
                a0 = pack2(xnA[0], 0.0f);
                a1 = pack2(xnA[1], 0.0f);
                if (step + 1 < T_SZ) {   // prefetch G1 xg for step+1
                    xnA[0] = g_xg[((size_t)(b0 + 2) * T_SZ + step + 1) * G_SZ + t];
                    if (r4)
                        xnA[1] = g_xg[((size_t)(b0 + 3) * T_SZ + step + 1) * G_SZ + t];
                }
            }

            // GEMM over rows 2,(3)
            const ulonglong2* h2 = (const ulonglong2*)&h_s[2][0];
#pragma unroll
            for (int q = 0; q < 16; q++) {
                ulonglong2 p2 = h2[q];
                a0 = ffma2(p2.x, w2[2 * q],     a0);
                a0 = ffma2(p2.y, w2[2 * q + 1], a0);
            }
            if (r4) {
#pragma unroll
                for (int q = 0; q < 16; q++) {
                    ulonglong2 p3 = h2[16 + q];
                    a1 = ffma2(p3.x, w2[2 * q],     a1);
                    a1 = ffma2(p3.y, w2[2 * q + 1], a1);
                }
            }

            // epilogue G0(step): rows 0,1 (warps 0-3)
            if (cellG0) {
                float hv = cell_update(&gates_s[re][0], je, c);
                h_s[re][je] = hv;
                if (MODE != 2)
                    g_h[((size_t)(b0 + re) * T_SZ + step) * H_SZ + je] = hv;
                else if (step == T_SZ - 1)
                    g_h[(size_t)(b0 + re) * H_SZ + je] = hv;
            }

            gates_s[2][t] = sum2(a0);
            if (r4) gates_s[3][t] = sum2(a1);
        }
        __syncthreads();

        // ---------------- phase B: GEMM G0(step+1) + epilogue G1(step) ------
        {
            if (step + 1 < T_SZ) {
                u64 a0, a1;
                if (MODE == 0) {
                    const int nxt = (step + 1) & 1;
                    float s0 = bias, s1 = bias;
#pragma unroll
                    for (int k = 0; k < I_SZ; k++) {
                        s0 = fmaf(xs[nxt][0][k], wx[k], s0);
                        s1 = fmaf(xs[nxt][1][k], wx[k], s1);
                    }
                    a0 = pack2(s0, 0.0f);
                    a1 = pack2(s1, 0.0f);
                } else {
                    a0 = pack2(xnB[0], 0.0f);
                    a1 = pack2(xnB[1], 0.0f);
                    if (step + 2 < T_SZ) {   // prefetch G0 xg for step+2
                        xnB[0] = g_xg[((size_t)(b0 + 0) * T_SZ + step + 2) * G_SZ + t];
                        xnB[1] = g_xg[((size_t)(b0 + 1) * T_SZ + step + 2) * G_SZ + t];
                    }
                }

                // GEMM over rows 0,1 with h(step) written in phase A
                const ulonglong2* h2 = (const ulonglong2*)&h_s[0][0];
#pragma unroll
                for (int q = 0; q < 16; q++) {
                    ulonglong2 p0 = h2[q];
                    a0 = ffma2(p0.x, w2[2 * q],     a0);
                    a0 = ffma2(p0.y, w2[2 * q + 1], a0);
                }
#pragma unroll
                for (int q = 0; q < 16; q++) {
                    ulonglong2 p1 = h2[16 + q];
                    a1 = ffma2(p1.x, w2[2 * q],     a1);
                    a1 = ffma2(p1.y, w2[2 * q + 1], a1);
                }

                // epilogue G1(step): rows 2,(3) (warps 4-7)
                if (cellG1) {
                    float hv = cell_update(&gates_s[re][0], je, c);
                    h_s[re][je] = hv;
                    if (MODE != 2)
                        g_h[((size_t)(b0 + re) * T_SZ + step) * H_SZ + je] = hv;
                    else if (step == T_SZ - 1)
                        g_h[(size_t)(b0 + re) * H_SZ + je] = hv;
                }

                gates_s[0][t] = sum2(a0);
                gates_s[1][t] = sum2(a1);
            } else {
                // last step: only the G1 epilogue remains
                if (cellG1) {
                    float hv = cell_update(&gates_s[re][0], je, c);
                    if (MODE != 2)
                        g_h[((size_t)(b0 + re) * T_SZ + step) * H_SZ + je] = hv;
                    else
                        g_h[(size_t)(b0 + re) * H_SZ + je] = hv;
                }
            }
        }
        __syncthreads();
    }
}

// ---------------------------------------------------------------------------
// Final FC: out[b] = h_last[b,:] . w_fc + b_fc   (O=1)
// ---------------------------------------------------------------------------
__global__ __launch_bounds__(256) void fc_kernel(const float* __restrict__ wfc,
                                                 const float* __restrict__ bfc,
                                                 float* __restrict__ out)
{
    int b = blockIdx.x * 256 + threadIdx.x;
    float acc = bfc[0];
#pragma unroll
    for (int q = 0; q < 16; q++) {
        float4 hv = *(const float4*)&g_h[b * H_SZ + q * 4];
        float4 wv = *(const float4*)&wfc[q * 4];
        acc = fmaf(hv.x, wv.x, acc);
        acc = fmaf(hv.y, wv.y, acc);
        acc = fmaf(hv.z, wv.z, acc);
        acc = fmaf(hv.w, wv.w, acc);
    }
    out[b] = acc;
}

// ---------------------------------------------------------------------------
extern "C" void kernel_launch(void* const* d_in, const int* in_sizes, int n_in,
                              void* d_out, int out_size)
{
    (void)in_sizes; (void)n_in; (void)out_size;
    const float* x     = (const float*)d_in[0];
    const float* w_ih0 = (const float*)d_in[1];
    const float* w_hh0 = (const float*)d_in[2];
    const float* b_ih0 = (const float*)d_in[3];
    const float* b_hh0 = (const float*)d_in[4];
    const float* w_ih1 = (const float*)d_in[5];
    const float* w_hh1 = (const float*)d_in[6];
    const float* b_ih1 = (const float*)d_in[7];
    const float* b_hh1 = (const float*)d_in[8];
    const float* w_ih2 = (const float*)d_in[9];
    const float* w_hh2 = (const float*)d_in[10];
    const float* b_ih2 = (const float*)d_in[11];
    const float* b_hh2 = (const float*)d_in[12];
    const float* w_fc  = (const float*)d_in[13];
    const float* b_fc  = (const float*)d_in[14];
    float* out = (float*)d_out;

    const int NROWS = B_SZ * T_SZ;  // 262144

    cudaFuncSetAttribute(xg_gemm64, cudaFuncAttributeMaxDynamicSharedMemorySize,
                         XG_SMEM_BYTES);

    // layer 0 (xg fused into rec)
    lstm_rec<0><<<GRID_REC, 256>>>(w_hh0, x, w_ih0, b_ih0, b_hh0);

    // layer 1
    transpose_w<<<64, 256>>>(w_ih1);
    xg_gemm64<<<NROWS / 64, 256, XG_SMEM_BYTES>>>(b_ih1, b_hh1);
    lstm_rec<1><<<GRID_REC, 256>>>(w_hh1, nullptr, nullptr, nullptr, nullptr);

    // layer 2 (only last timestep's h needed downstream)
    transpose_w<<<64, 256>>>(w_ih2);
    xg_gemm64<<<NROWS / 64, 256, XG_SMEM_BYTES>>>(b_ih2, b_hh2);
    lstm_rec<2><<<GRID_REC, 256>>>(w_hh2, nullptr, nullptr, nullptr, nullptr);

    // final projection
    fc_kernel<<<B_SZ / 256, 256>>>(w_fc, b_fc, out);
}